// round 6
// baseline (speedup 1.0000x reference)
#include <cuda_runtime.h>
#include <cuda_fp16.h>
#include <math.h>
#include <stdint.h>

// Problem constants
#define S_LEN   2048
#define BATCH   8
#define DIM     512
#define HID     512
#define N3      1536
#define MROWS   16384
#define NODES   7
#define NCHUNK  32
#define CHLEN   64
#define LANES   4096
#define LANES2  2048      // each scan thread handles 2 adjacent h

// GEMM tiling (mma.sync tf32, 128 threads / 4 warps, 64x64 warp tiles)
#define BM 128
#define BN 128
#define BK 16
#define APITCH 20
#define BPITCH 136
#define SBYTES 37888      // max(gemm staging 37888, tproj 28672)

#define GEMM_BLOCKS_PER_NODE (12 * 128)   // (N3/BN) * (MROWS/BM) = 1536

// Scratch (static __device__ arrays: allocation-free, graph-safe)
__device__ __align__(256) __half g_V [(size_t)NODES * MROWS * N3];   // 352 MB
__device__ __align__(256) __half g_Hh[(size_t)6 * MROWS * HID];      // 100 MB
__device__ __align__(256) float  g_T [(size_t)NODES * MROWS * 2];
__device__ __align__(256) float  g_A [(size_t)NODES * NCHUNK * LANES];
__device__ __align__(256) float  g_Bc[(size_t)NODES * NCHUNK * LANES];
__device__ __align__(256) float  g_CM[(size_t)NCHUNK * LANES];
__device__ __align__(256) float  g_Xr[(size_t)MROWS * DIM];          // tf32-rounded X
__device__ __align__(256) float  g_Wr[(size_t)NODES * DIM * N3];     // tf32-rounded W

__device__ __forceinline__ float sigmoidf(float x) {
    return 1.0f / (1.0f + expf(-x));
}
__device__ __forceinline__ float to_tf32(float x) {
    uint32_t r;
    asm("cvt.rna.tf32.f32 %0, %1;\n" : "=r"(r) : "f"(x));
    return __uint_as_float(r);
}
__device__ __forceinline__ uint32_t smem_u32(const void* p) {
    return (uint32_t)__cvta_generic_to_shared(p);
}
__device__ __forceinline__ void cp_async16(uint32_t dst, const void* src) {
    asm volatile("cp.async.cg.shared.global [%0], [%1], 16;\n" :: "r"(dst), "l"(src));
}
__device__ __forceinline__ void cp_commit() { asm volatile("cp.async.commit_group;\n"); }
template<int N> __device__ __forceinline__ void cp_wait() {
    asm volatile("cp.async.wait_group %0;\n" :: "n"(N));
}
__device__ __forceinline__ void mma_tf32(float* c, const uint32_t* a, const uint32_t* b) {
    asm volatile(
        "mma.sync.aligned.m16n8k8.row.col.f32.tf32.tf32.f32 "
        "{%0,%1,%2,%3}, {%4,%5,%6,%7}, {%8,%9}, {%0,%1,%2,%3};\n"
        : "+f"(c[0]), "+f"(c[1]), "+f"(c[2]), "+f"(c[3])
        : "r"(a[0]), "r"(a[1]), "r"(a[2]), "r"(a[3]), "r"(b[0]), "r"(b[1]));
}

// ---------------------------------------------------------------------------
__global__ void noop_kernel() {}

__global__ __launch_bounds__(256) void xround_kernel(const float* __restrict__ X) {
    const int i = blockIdx.x * 256 + threadIdx.x;
    const float4 v = *(const float4*)(X + (size_t)i * 4);
    *(float4*)(g_Xr + (size_t)i * 4) =
        make_float4(to_tf32(v.x), to_tf32(v.y), to_tf32(v.z), to_tf32(v.w));
}
__global__ __launch_bounds__(256) void wround_kernel(const float* __restrict__ Wp) {
    const int i = blockIdx.x * 256 + threadIdx.x;
    const float4 v = *(const float4*)(Wp + (size_t)i * 4);
    *(float4*)(g_Wr + (size_t)i * 4) =
        make_float4(to_tf32(v.x), to_tf32(v.y), to_tf32(v.z), to_tf32(v.w));
}

// ---------------------------------------------------------------------------
// GEMM body: V[node] tile (mb, nb) = Xr @ Wr[node], fp16 store.
// ---------------------------------------------------------------------------
__device__ __forceinline__ void gemm_stage_load(uint32_t aB, uint32_t bB,
                                                const float* __restrict__ Ag,
                                                const float* __restrict__ Bg,
                                                int k0, int tid) {
    const uint32_t dA = aB + (uint32_t)(tid * APITCH) * 4u;
    const float* srcA = Ag + (size_t)tid * DIM + k0;
    #pragma unroll
    for (int kc = 0; kc < 4; kc++) cp_async16(dA + kc * 16u, srcA + kc * 4);
    #pragma unroll
    for (int i = 0; i < 4; i++) {
        const int cid = i * 128 + tid;
        const int kb = cid >> 5, nc = cid & 31;
        cp_async16(bB + (uint32_t)(kb * BPITCH + nc * 4) * 4u,
                   Bg + (size_t)(k0 + kb) * N3 + nc * 4);
    }
    cp_commit();
}

__device__ __forceinline__ void gemm_body(char* sbuf, int node, int mb, int nb, int tid) {
    float* sA = (float*)sbuf;                    // 2 stages x BM*APITCH floats
    float* sB = (float*)(sbuf + 20480);          // 2 stages x BK*BPITCH floats
    const int n0 = nb * BN;
    const int m0 = mb * BM;
    const float* Ag = g_Xr + (size_t)m0 * DIM;
    const float* Bg = g_Wr + (size_t)node * DIM * N3 + n0;
    __half* C = g_V + (size_t)node * MROWS * N3;

    const int w = tid >> 5;
    const int lane = tid & 31;
    const int gid = lane >> 2;
    const int tig = lane & 3;
    const int wm = (w >> 1) * 64;
    const int wn = (w & 1) * 64;

    const uint32_t sAu = smem_u32(sA);
    const uint32_t sBu = smem_u32(sB);

    float acc[4][8][4];
    #pragma unroll
    for (int mi = 0; mi < 4; mi++)
        #pragma unroll
        for (int ni = 0; ni < 8; ni++)
            #pragma unroll
            for (int c = 0; c < 4; c++) acc[mi][ni][c] = 0.0f;

    gemm_stage_load(sAu, sBu, Ag, Bg, 0, tid);

    #pragma unroll 1
    for (int kt = 0; kt < 32; kt++) {
        const int s = kt & 1;
        const bool more = (kt + 1 < 32);
        if (more) {
            const int ns = s ^ 1;
            gemm_stage_load(sAu + (uint32_t)(ns * BM * APITCH) * 4u,
                            sBu + (uint32_t)(ns * BK * BPITCH) * 4u,
                            Ag, Bg, (kt + 1) * BK, tid);
            cp_wait<1>();
        } else {
            cp_wait<0>();
        }
        __syncthreads();

        const float* As = sA + s * BM * APITCH;
        const float* Bs = sB + s * BK * BPITCH;
        #pragma unroll
        for (int kk = 0; kk < 16; kk += 8) {
            uint32_t a[4][4], b[8][2];
            #pragma unroll
            for (int mi = 0; mi < 4; mi++) {
                const int m = wm + mi * 16 + gid;
                a[mi][0] = __float_as_uint(As[m * APITCH + kk + tig]);
                a[mi][1] = __float_as_uint(As[(m + 8) * APITCH + kk + tig]);
                a[mi][2] = __float_as_uint(As[m * APITCH + kk + tig + 4]);
                a[mi][3] = __float_as_uint(As[(m + 8) * APITCH + kk + tig + 4]);
            }
            #pragma unroll
            for (int ni = 0; ni < 8; ni++) {
                const int n = wn + ni * 8 + gid;
                b[ni][0] = __float_as_uint(Bs[(kk + tig) * BPITCH + n]);
                b[ni][1] = __float_as_uint(Bs[(kk + tig + 4) * BPITCH + n]);
            }
            #pragma unroll
            for (int mi = 0; mi < 4; mi++)
                #pragma unroll
                for (int ni = 0; ni < 8; ni++)
                    mma_tf32(acc[mi][ni], a[mi], b[ni]);
        }
        __syncthreads();
    }

    #pragma unroll
    for (int mi = 0; mi < 4; mi++) {
        #pragma unroll
        for (int ni = 0; ni < 8; ni++) {
            const int row = m0 + wm + mi * 16 + gid;
            const int col = n0 + wn + ni * 8 + tig * 2;
            *(__half2*)&C[(size_t)row * N3 + col] =
                __floats2half2_rn(acc[mi][ni][0], acc[mi][ni][1]);
            *(__half2*)&C[(size_t)(row + 8) * N3 + col] =
                __floats2half2_rn(acc[mi][ni][2], acc[mi][ni][3]);
        }
    }
}

// ---------------------------------------------------------------------------
// tproj body: all 7 nodes' gates in one X pass (W_T in smem overlay)
// ---------------------------------------------------------------------------
__device__ __forceinline__ void tproj_body(char* sbuf, int blk,
                                           const float* __restrict__ X,
                                           const float* __restrict__ WT,
                                           const float* __restrict__ bT, int tid) {
    float (*swt)[NODES][DIM] = (float (*)[NODES][DIM])sbuf;   // 28 KB
    for (int idx = tid; idx < NODES * DIM * 2; idx += 128) {
        const int node = idx / (DIM * 2);
        const int r = idx - node * DIM * 2;
        swt[r & 1][node][r >> 1] = WT[idx];
    }
    __syncthreads();

    const int w = tid >> 5;
    const int lane = tid & 31;
    const int m0 = blk * 128 + w * 32;

    float bt[NODES][2];
    #pragma unroll
    for (int n = 0; n < NODES; n++) {
        bt[n][0] = bT[n * 2 + 0];
        bt[n][1] = bT[n * 2 + 1];
    }
    for (int r = 0; r < 32; r++) {
        const int m = m0 + r;
        const float* xr = X + (size_t)m * DIM;
        float s[NODES][2];
        #pragma unroll
        for (int n = 0; n < NODES; n++) s[n][0] = s[n][1] = 0.0f;
        #pragma unroll 4
        for (int k = lane; k < DIM; k += 32) {
            const float x = xr[k];
            #pragma unroll
            for (int n = 0; n < NODES; n++) {
                s[n][0] = fmaf(x, swt[0][n][k], s[n][0]);
                s[n][1] = fmaf(x, swt[1][n][k], s[n][1]);
            }
        }
        #pragma unroll
        for (int n = 0; n < NODES; n++)
            #pragma unroll
            for (int j = 0; j < 2; j++)
                #pragma unroll
                for (int o = 16; o > 0; o >>= 1)
                    s[n][j] += __shfl_down_sync(0xFFFFFFFFu, s[n][j], o);
        if (lane == 0) {
            #pragma unroll
            for (int n = 0; n < NODES; n++) {
                const size_t t = ((size_t)n * MROWS + m) * 2;
                g_T[t + 0] = sigmoidf(s[n][0] + bt[n][0]);
                g_T[t + 1] = sigmoidf(s[n][1] + bt[n][1]);
            }
        }
    }
}

// ---------------------------------------------------------------------------
// scan bodies (fp16 V/H, 2 h-lanes per thread)
// ---------------------------------------------------------------------------
template<bool INTERNAL>
__device__ __forceinline__ void scanA_body(int node, int chunk, int l2) {
    const int b = l2 >> 8;
    const int h0 = (l2 & 255) * 2;
    const __half* Vn = g_V + (size_t)node * MROWS * N3;
    const float* Tn = g_T + (size_t)node * MROWS * 2;
    const __half* HF = g_Hh + (size_t)(2 * node) * MROWS * HID;   // child 2i+1 -> slot 2i

    float A0 = 1.0f, B0 = 0.0f, A1 = 1.0f, B1 = 0.0f;
    const int s0 = chunk * CHLEN;
    #pragma unroll 4
    for (int si = 0; si < CHLEN; si++) {
        const int m = (s0 + si) * BATCH + b;
        const size_t vi = (size_t)m * N3 + h0;
        float2 z = __half22float2(*(const __half2*)(Vn + vi));
        float2 f = __half22float2(*(const __half2*)(Vn + vi + HID));
        if (INTERNAL) {
            const float t1 = __ldg(Tn + (size_t)m * 2);
            float2 hf = __half22float2(*(const __half2*)(HF + (size_t)m * HID + h0));
            f.x = hf.x * t1 + (1.0f - t1) * f.x;
            f.y = hf.y * t1 + (1.0f - t1) * f.y;
        }
        z.x = fmaxf(z.x, 0.0f); z.y = fmaxf(z.y, 0.0f);
        f.x = sigmoidf(f.x);    f.y = sigmoidf(f.y);
        const float a0 = 1.0f - f.x, a1 = 1.0f - f.y;
        A0 *= a0; B0 = fmaf(a0, B0, f.x * z.x);
        A1 *= a1; B1 = fmaf(a1, B1, f.y * z.y);
    }
    const size_t idx = ((size_t)node * NCHUNK + chunk) * LANES + b * 512 + h0;
    *(float2*)&g_A[idx]  = make_float2(A0, A1);
    *(float2*)&g_Bc[idx] = make_float2(B0, B1);
}

template<bool INTERNAL, bool ROOT>
__device__ __forceinline__ void scanB_body(int node, int chunk, int l2,
                                           const float* __restrict__ X,
                                           float* __restrict__ out) {
    const int b = l2 >> 8;
    const int h0 = (l2 & 255) * 2;
    const int L = b * 512 + h0;
    const __half* Vn = g_V + (size_t)node * MROWS * N3;
    const float* Tn = g_T + (size_t)node * MROWS * 2;
    const __half* HF = g_Hh + (size_t)(2 * node) * MROWS * HID;
    const __half* HO = g_Hh + (size_t)(2 * node + 1) * MROWS * HID;
    __half* Hn = g_Hh + (size_t)(node - 1) * MROWS * HID;   // unused when ROOT

    // self-computed chunk prefix (replaces scanMid/g_Cin)
    float c0 = 0.0f, c1 = 0.0f;
    {
        const float* Ap = g_A  + (size_t)node * NCHUNK * LANES + L;
        const float* Bp = g_Bc + (size_t)node * NCHUNK * LANES + L;
        for (int j = 0; j < chunk; j++) {
            const float2 a  = *(const float2*)(Ap + (size_t)j * LANES);
            const float2 bb = *(const float2*)(Bp + (size_t)j * LANES);
            c0 = fmaf(a.x, c0, bb.x);
            c1 = fmaf(a.y, c1, bb.y);
        }
    }

    float cm0 = -3.4e38f, cm1 = -3.4e38f;
    const int s0 = chunk * CHLEN;
    #pragma unroll 2
    for (int si = 0; si < CHLEN; si++) {
        const int m = (s0 + si) * BATCH + b;
        const size_t vi = (size_t)m * N3 + h0;
        float2 z = __half22float2(*(const __half2*)(Vn + vi));
        float2 f = __half22float2(*(const __half2*)(Vn + vi + HID));
        float2 o = __half22float2(*(const __half2*)(Vn + vi + 2 * HID));
        if (INTERNAL) {
            const float2 t = *(const float2*)(Tn + (size_t)m * 2);
            float2 hf = __half22float2(*(const __half2*)(HF + (size_t)m * HID + h0));
            float2 ho2 = __half22float2(*(const __half2*)(HO + (size_t)m * HID + h0));
            f.x = hf.x * t.x + (1.0f - t.x) * f.x;
            f.y = hf.y * t.x + (1.0f - t.x) * f.y;
            o.x = ho2.x * t.y + (1.0f - t.y) * o.x;
            o.y = ho2.y * t.y + (1.0f - t.y) * o.y;
        }
        z.x = fmaxf(z.x, 0.0f); z.y = fmaxf(z.y, 0.0f);
        f.x = sigmoidf(f.x);    f.y = sigmoidf(f.y);
        c0 = fmaf(f.x, z.x, (1.0f - f.x) * c0);
        c1 = fmaf(f.y, z.y, (1.0f - f.y) * c1);
        const float v0 = c0 * sigmoidf(o.x);
        const float v1 = c1 * sigmoidf(o.y);
        const float2 xr = *(const float2*)(X + (size_t)m * DIM + h0);
        if (ROOT) {
            cm0 = fmaxf(cm0, v0);
            cm1 = fmaxf(cm1, v1);
            *(float2*)&out[(size_t)m * HID + h0] = make_float2(v0 + xr.x, v1 + xr.y);
        } else {
            *(__half2*)&Hn[(size_t)m * HID + h0] = __floats2half2_rn(v0 + xr.x, v1 + xr.y);
        }
    }
    if (ROOT)
        *(float2*)&g_CM[(size_t)chunk * LANES + L] = make_float2(cm0, cm1);
}

// ---------------------------------------------------------------------------
// Fused kernels
// ---------------------------------------------------------------------------
// K1: gemm(nodes 3..6) + tproj
__global__ __launch_bounds__(128) void k1_kernel(const float* __restrict__ X,
                                                 const float* __restrict__ WT,
                                                 const float* __restrict__ bT) {
    __shared__ __align__(16) char sbuf[SBYTES];
    const int bid = blockIdx.x;
    const int tid = threadIdx.x;
    if (bid < 4 * GEMM_BLOCKS_PER_NODE) {
        const int node = 3 + bid / GEMM_BLOCKS_PER_NODE;
        const int r = bid % GEMM_BLOCKS_PER_NODE;
        gemm_body(sbuf, node, r / 12, r % 12, tid);
    } else {
        tproj_body(sbuf, bid - 4 * GEMM_BLOCKS_PER_NODE, X, WT, bT, tid);
    }
}

// K2: gemm(nodes 0..2) + scanA(leaves 3..6)
__global__ __launch_bounds__(128) void k2_kernel() {
    __shared__ __align__(16) char sbuf[SBYTES];
    const int bid = blockIdx.x;
    const int tid = threadIdx.x;
    if (bid < 3 * GEMM_BLOCKS_PER_NODE) {
        const int node = bid / GEMM_BLOCKS_PER_NODE;
        const int r = bid % GEMM_BLOCKS_PER_NODE;
        gemm_body(sbuf, node, r / 12, r % 12, tid);
    } else {
        const int sid = bid - 3 * GEMM_BLOCKS_PER_NODE;   // 0..2047
        const int node = 3 + (sid >> 9);
        const int r = sid & 511;
        scanA_body<false>(node, r >> 4, (r & 15) * 128 + tid);
    }
}

// standalone scan kernels: grid (16, NCHUNK, n_nodes)
template<bool INTERNAL>
__global__ __launch_bounds__(128) void scanA_kernel(int first_node) {
    scanA_body<INTERNAL>(first_node + blockIdx.z, blockIdx.y,
                         blockIdx.x * 128 + threadIdx.x);
}
template<bool INTERNAL, bool ROOT>
__global__ __launch_bounds__(128) void scanB_kernel(int first_node,
                                                    const float* __restrict__ X,
                                                    float* __restrict__ out) {
    scanB_body<INTERNAL, ROOT>(first_node + blockIdx.z, blockIdx.y,
                               blockIdx.x * 128 + threadIdx.x, X, out);
}

__global__ __launch_bounds__(128) void cmax_kernel(float* __restrict__ cmax_out) {
    const int lane = blockIdx.x * 128 + threadIdx.x;
    float cm = -3.4e38f;
    #pragma unroll
    for (int j = 0; j < NCHUNK; j++)
        cm = fmaxf(cm, g_CM[(size_t)j * LANES + lane]);
    cmax_out[lane] = cm;
}

// ---------------------------------------------------------------------------
extern "C" void kernel_launch(void* const* d_in, const int* in_sizes, int n_in,
                              void* d_out, int out_size) {
    const float* X  = (const float*)d_in[0];
    const float* Wp = (const float*)d_in[1];
    const float* WT = (const float*)d_in[2];
    const float* bT = (const float*)d_in[3];
    float* out = (float*)d_out;
    (void)in_sizes; (void)n_in;

    // 1-5: prep + padding so K1 (pure-ish GEMM) is launch #6 for ncu -s 5 -c 1
    xround_kernel<<<(MROWS * DIM / 4) / 256, 256>>>(X);
    wround_kernel<<<(NODES * DIM * N3 / 4) / 256, 256>>>(Wp);
    noop_kernel<<<1, 32>>>();
    noop_kernel<<<1, 32>>>();
    noop_kernel<<<1, 32>>>();

    // 6: gemm leaves + tproj
    k1_kernel<<<4 * GEMM_BLOCKS_PER_NODE + MROWS / 128, 128>>>(X, WT, bT);
    // 7: gemm internal nodes + scanA leaves (ride-along)
    k2_kernel<<<3 * GEMM_BLOCKS_PER_NODE + 4 * NCHUNK * (LANES2 / 128), 128>>>();
    // 8: scanB leaves
    scanB_kernel<false, false><<<dim3(LANES2 / 128, NCHUNK, 4), 128>>>(3, X, out);
    // 9-10: level 2 (nodes 1,2)
    scanA_kernel<true><<<dim3(LANES2 / 128, NCHUNK, 2), 128>>>(1);
    scanB_kernel<true, false><<<dim3(LANES2 / 128, NCHUNK, 2), 128>>>(1, X, out);
    // 11-12: root (node 0)
    scanA_kernel<true><<<dim3(LANES2 / 128, NCHUNK, 1), 128>>>(0);
    scanB_kernel<true, true><<<dim3(LANES2 / 128, NCHUNK, 1), 128>>>(0, X, out);
    // 13: cmax second output
    if (out_size >= MROWS * HID + LANES)
        cmax_kernel<<<LANES / 128, 128>>>(out + (size_t)MROWS * HID);
}

// round 7
// speedup vs baseline: 1.0978x; 1.0978x over previous
#include <cuda_runtime.h>
#include <cuda_fp16.h>
#include <math.h>
#include <stdint.h>

// Problem constants
#define S_LEN   2048
#define BATCH   8
#define DIM     512
#define HID     512
#define N3      1536
#define MROWS   16384
#define NODES   7
#define NCHUNK  32
#define CHLEN   64
#define LANES   4096
#define LANES2  2048      // scan threads handle 2 adjacent h

// GEMM tiling (mma.sync tf32, 128 threads / 4 warps, 64x64 warp tiles)
#define BM 128
#define BN 128
#define BK 16
#define APITCH 20
#define BPITCH 136

// Scratch (static __device__ arrays: allocation-free, graph-safe)
__device__ __align__(256) __half g_V [(size_t)NODES * MROWS * N3];
__device__ __align__(256) __half g_Hh[(size_t)6 * MROWS * HID];
__device__ __align__(256) float  g_T [(size_t)NODES * MROWS * 2];
__device__ __align__(256) float  g_A [(size_t)NODES * NCHUNK * LANES];
__device__ __align__(256) float  g_Bc[(size_t)NODES * NCHUNK * LANES];
__device__ __align__(256) float  g_CM[(size_t)NCHUNK * LANES];
__device__ __align__(256) float  g_Xr[(size_t)MROWS * DIM];
__device__ __align__(256) float  g_Wr[(size_t)NODES * DIM * N3];

__device__ __forceinline__ float sigmoidf(float x) {
    return __fdividef(1.0f, 1.0f + __expf(-x));
}
__device__ __forceinline__ float to_tf32(float x) {
    uint32_t r;
    asm("cvt.rna.tf32.f32 %0, %1;\n" : "=r"(r) : "f"(x));
    return __uint_as_float(r);
}
__device__ __forceinline__ uint32_t smem_u32(const void* p) {
    return (uint32_t)__cvta_generic_to_shared(p);
}
__device__ __forceinline__ void cp_async16(uint32_t dst, const void* src) {
    asm volatile("cp.async.cg.shared.global [%0], [%1], 16;\n" :: "r"(dst), "l"(src));
}
__device__ __forceinline__ void cp_commit() { asm volatile("cp.async.commit_group;\n"); }
template<int N> __device__ __forceinline__ void cp_wait() {
    asm volatile("cp.async.wait_group %0;\n" :: "n"(N));
}
__device__ __forceinline__ void mma_tf32(float* c, const uint32_t* a, const uint32_t* b) {
    asm volatile(
        "mma.sync.aligned.m16n8k8.row.col.f32.tf32.tf32.f32 "
        "{%0,%1,%2,%3}, {%4,%5,%6,%7}, {%8,%9}, {%0,%1,%2,%3};\n"
        : "+f"(c[0]), "+f"(c[1]), "+f"(c[2]), "+f"(c[3])
        : "r"(a[0]), "r"(a[1]), "r"(a[2]), "r"(a[3]), "r"(b[0]), "r"(b[1]));
}

// ---------------------------------------------------------------------------
__global__ __launch_bounds__(256) void xround_kernel(const float* __restrict__ X) {
    const int i = blockIdx.x * 256 + threadIdx.x;
    const float4 v = *(const float4*)(X + (size_t)i * 4);
    *(float4*)(g_Xr + (size_t)i * 4) =
        make_float4(to_tf32(v.x), to_tf32(v.y), to_tf32(v.z), to_tf32(v.w));
}
__global__ __launch_bounds__(256) void wround_kernel(const float* __restrict__ Wp) {
    const int i = blockIdx.x * 256 + threadIdx.x;
    const float4 v = *(const float4*)(Wp + (size_t)i * 4);
    *(float4*)(g_Wr + (size_t)i * 4) =
        make_float4(to_tf32(v.x), to_tf32(v.y), to_tf32(v.z), to_tf32(v.w));
}

// ---------------------------------------------------------------------------
// T projection: all 7 nodes' gates in one X pass (W_T in smem)
// ---------------------------------------------------------------------------
__global__ __launch_bounds__(128) void tproj_kernel(const float* __restrict__ X,
                                                    const float* __restrict__ WT,
                                                    const float* __restrict__ bT) {
    __shared__ float swt[2][NODES][DIM];
    const int tid = threadIdx.x;
    for (int idx = tid; idx < NODES * DIM * 2; idx += 128) {
        const int node = idx / (DIM * 2);
        const int r = idx - node * DIM * 2;
        swt[r & 1][node][r >> 1] = WT[idx];
    }
    __syncthreads();

    const int w = tid >> 5;
    const int lane = tid & 31;
    const int m0 = blockIdx.x * 128 + w * 32;

    float bt[NODES][2];
    #pragma unroll
    for (int n = 0; n < NODES; n++) {
        bt[n][0] = bT[n * 2 + 0];
        bt[n][1] = bT[n * 2 + 1];
    }
    for (int r = 0; r < 32; r++) {
        const int m = m0 + r;
        const float* xr = X + (size_t)m * DIM;
        float s[NODES][2];
        #pragma unroll
        for (int n = 0; n < NODES; n++) s[n][0] = s[n][1] = 0.0f;
        #pragma unroll 4
        for (int k = lane; k < DIM; k += 32) {
            const float x = xr[k];
            #pragma unroll
            for (int n = 0; n < NODES; n++) {
                s[n][0] = fmaf(x, swt[0][n][k], s[n][0]);
                s[n][1] = fmaf(x, swt[1][n][k], s[n][1]);
            }
        }
        #pragma unroll
        for (int n = 0; n < NODES; n++)
            #pragma unroll
            for (int j = 0; j < 2; j++)
                #pragma unroll
                for (int o = 16; o > 0; o >>= 1)
                    s[n][j] += __shfl_down_sync(0xFFFFFFFFu, s[n][j], o);
        if (lane == 0) {
            #pragma unroll
            for (int n = 0; n < NODES; n++) {
                const size_t t = ((size_t)n * MROWS + m) * 2;
                g_T[t + 0] = sigmoidf(s[n][0] + bt[n][0]);
                g_T[t + 1] = sigmoidf(s[n][1] + bt[n][1]);
            }
        }
    }
}

// ---------------------------------------------------------------------------
// Tensor-core GEMM (all 7 nodes): V[node] = Xr @ Wr[node], fp16 store.
// ---------------------------------------------------------------------------
__device__ __forceinline__ void gemm_stage_load(uint32_t aB, uint32_t bB,
                                                const float* __restrict__ Ag,
                                                const float* __restrict__ Bg,
                                                int k0, int tid) {
    const uint32_t dA = aB + (uint32_t)(tid * APITCH) * 4u;
    const float* srcA = Ag + (size_t)tid * DIM + k0;
    #pragma unroll
    for (int kc = 0; kc < 4; kc++) cp_async16(dA + kc * 16u, srcA + kc * 4);
    #pragma unroll
    for (int i = 0; i < 4; i++) {
        const int cid = i * 128 + tid;
        const int kb = cid >> 5, nc = cid & 31;
        cp_async16(bB + (uint32_t)(kb * BPITCH + nc * 4) * 4u,
                   Bg + (size_t)(k0 + kb) * N3 + nc * 4);
    }
    cp_commit();
}

__global__ __launch_bounds__(128) void gemm_tc_kernel() {
    __shared__ __align__(16) float sA[2][BM * APITCH];
    __shared__ __align__(16) float sB[2][BK * BPITCH];

    const int node = blockIdx.z;
    const int n0 = blockIdx.x * BN;
    const int m0 = blockIdx.y * BM;
    const float* Ag = g_Xr + (size_t)m0 * DIM;
    const float* Bg = g_Wr + (size_t)node * DIM * N3 + n0;
    __half* C = g_V + (size_t)node * MROWS * N3;

    const int tid = threadIdx.x;
    const int w = tid >> 5;
    const int lane = tid & 31;
    const int gid = lane >> 2;
    const int tig = lane & 3;
    const int wm = (w >> 1) * 64;
    const int wn = (w & 1) * 64;

    const uint32_t sAu = smem_u32(&sA[0][0]);
    const uint32_t sBu = smem_u32(&sB[0][0]);

    float acc[4][8][4];
    #pragma unroll
    for (int mi = 0; mi < 4; mi++)
        #pragma unroll
        for (int ni = 0; ni < 8; ni++)
            #pragma unroll
            for (int c = 0; c < 4; c++) acc[mi][ni][c] = 0.0f;

    gemm_stage_load(sAu, sBu, Ag, Bg, 0, tid);

    #pragma unroll 1
    for (int kt = 0; kt < 32; kt++) {
        const int s = kt & 1;
        const bool more = (kt + 1 < 32);
        if (more) {
            const int ns = s ^ 1;
            gemm_stage_load(sAu + (uint32_t)(ns * BM * APITCH) * 4u,
                            sBu + (uint32_t)(ns * BK * BPITCH) * 4u,
                            Ag, Bg, (kt + 1) * BK, tid);
            cp_wait<1>();
        } else {
            cp_wait<0>();
        }
        __syncthreads();

        const float* As = &sA[s][0];
        const float* Bs = &sB[s][0];
        #pragma unroll
        for (int kk = 0; kk < 16; kk += 8) {
            uint32_t a[4][4], b[8][2];
            #pragma unroll
            for (int mi = 0; mi < 4; mi++) {
                const int m = wm + mi * 16 + gid;
                a[mi][0] = __float_as_uint(As[m * APITCH + kk + tig]);
                a[mi][1] = __float_as_uint(As[(m + 8) * APITCH + kk + tig]);
                a[mi][2] = __float_as_uint(As[m * APITCH + kk + tig + 4]);
                a[mi][3] = __float_as_uint(As[(m + 8) * APITCH + kk + tig + 4]);
            }
            #pragma unroll
            for (int ni = 0; ni < 8; ni++) {
                const int n = wn + ni * 8 + gid;
                b[ni][0] = __float_as_uint(Bs[(kk + tig) * BPITCH + n]);
                b[ni][1] = __float_as_uint(Bs[(kk + tig + 4) * BPITCH + n]);
            }
            #pragma unroll
            for (int mi = 0; mi < 4; mi++)
                #pragma unroll
                for (int ni = 0; ni < 8; ni++)
                    mma_tf32(acc[mi][ni], a[mi], b[ni]);
        }
        __syncthreads();
    }

    #pragma unroll
    for (int mi = 0; mi < 4; mi++) {
        #pragma unroll
        for (int ni = 0; ni < 8; ni++) {
            const int row = m0 + wm + mi * 16 + gid;
            const int col = n0 + wn + ni * 8 + tig * 2;
            *(__half2*)&C[(size_t)row * N3 + col] =
                __floats2half2_rn(acc[mi][ni][0], acc[mi][ni][1]);
            *(__half2*)&C[(size_t)(row + 8) * N3 + col] =
                __floats2half2_rn(acc[mi][ni][2], acc[mi][ni][3]);
        }
    }
}

// ---------------------------------------------------------------------------
// scanA for leaves (affine chunk summaries of nodes 3..6)
// ---------------------------------------------------------------------------
__global__ __launch_bounds__(128) void scanA_leaf_kernel() {
    const int node  = 3 + blockIdx.z;
    const int chunk = blockIdx.y;
    const int l2    = blockIdx.x * 128 + threadIdx.x;
    const int b = l2 >> 8;
    const int h0 = (l2 & 255) * 2;
    const __half* Vn = g_V + (size_t)node * MROWS * N3;

    float A0 = 1.0f, B0 = 0.0f, A1 = 1.0f, B1 = 0.0f;
    const int s0 = chunk * CHLEN;
    #pragma unroll 4
    for (int si = 0; si < CHLEN; si++) {
        const int m = (s0 + si) * BATCH + b;
        const size_t vi = (size_t)m * N3 + h0;
        float2 z = __half22float2(*(const __half2*)(Vn + vi));
        float2 f = __half22float2(*(const __half2*)(Vn + vi + HID));
        z.x = fmaxf(z.x, 0.0f); z.y = fmaxf(z.y, 0.0f);
        f.x = sigmoidf(f.x);    f.y = sigmoidf(f.y);
        const float a0 = 1.0f - f.x, a1 = 1.0f - f.y;
        A0 *= a0; B0 = fmaf(a0, B0, f.x * z.x);
        A1 *= a1; B1 = fmaf(a1, B1, f.y * z.y);
    }
    const size_t idx = ((size_t)node * NCHUNK + chunk) * LANES + b * 512 + h0;
    *(float2*)&g_A[idx]  = make_float2(A0, A1);
    *(float2*)&g_Bc[idx] = make_float2(B0, B1);
}

// ---------------------------------------------------------------------------
// Level kernel: scanB(children c1=2p+1, c2=2p+2) fused with scanA(parent p).
// h of F-child feeds parent's A-pass in-register.
// CI = children are internal nodes (have their own H merges).
// ---------------------------------------------------------------------------
template<bool CI>
__global__ __launch_bounds__(128) void klevel_kernel(int p0, const float* __restrict__ X) {
    const int p  = p0 + blockIdx.z;
    const int c1 = 2 * p + 1;
    const int c2 = 2 * p + 2;
    const int chunk = blockIdx.y;
    const int l2 = blockIdx.x * 128 + threadIdx.x;
    const int b = l2 >> 8;
    const int h0 = (l2 & 255) * 2;
    const int L = b * 512 + h0;

    const __half* V1 = g_V + (size_t)c1 * MROWS * N3;
    const __half* V2 = g_V + (size_t)c2 * MROWS * N3;
    const __half* Vp = g_V + (size_t)p  * MROWS * N3;
    const float* T1 = g_T + (size_t)c1 * MROWS * 2;
    const float* T2 = g_T + (size_t)c2 * MROWS * 2;
    const float* Tp = g_T + (size_t)p  * MROWS * 2;
    // grandchildren H (only used when CI)
    const __half* G1F = g_Hh + (size_t)(2 * c1) * MROWS * HID;
    const __half* G1O = g_Hh + (size_t)(2 * c1 + 1) * MROWS * HID;
    const __half* G2F = g_Hh + (size_t)(2 * c2) * MROWS * HID;
    const __half* G2O = g_Hh + (size_t)(2 * c2 + 1) * MROWS * HID;
    __half* Ho1 = g_Hh + (size_t)(c1 - 1) * MROWS * HID;
    __half* Ho2 = g_Hh + (size_t)(c2 - 1) * MROWS * HID;

    // chunk prefixes for c1, c2
    float p10 = 0.0f, p11 = 0.0f, p20 = 0.0f, p21 = 0.0f;
    {
        const float* A1p = g_A  + (size_t)c1 * NCHUNK * LANES + L;
        const float* B1p = g_Bc + (size_t)c1 * NCHUNK * LANES + L;
        const float* A2p = g_A  + (size_t)c2 * NCHUNK * LANES + L;
        const float* B2p = g_Bc + (size_t)c2 * NCHUNK * LANES + L;
        for (int j = 0; j < chunk; j++) {
            const float2 a1 = *(const float2*)(A1p + (size_t)j * LANES);
            const float2 b1 = *(const float2*)(B1p + (size_t)j * LANES);
            const float2 a2 = *(const float2*)(A2p + (size_t)j * LANES);
            const float2 b2 = *(const float2*)(B2p + (size_t)j * LANES);
            p10 = fmaf(a1.x, p10, b1.x);
            p11 = fmaf(a1.y, p11, b1.y);
            p20 = fmaf(a2.x, p20, b2.x);
            p21 = fmaf(a2.y, p21, b2.y);
        }
    }

    float PA0 = 1.0f, PB0 = 0.0f, PA1 = 1.0f, PB1 = 0.0f;  // parent summary
    const int s0 = chunk * CHLEN;
    #pragma unroll 2
    for (int si = 0; si < CHLEN; si++) {
        const int m = (s0 + si) * BATCH + b;
        const float2 xr = *(const float2*)(X + (size_t)m * DIM + h0);

        // ---- child 1 (F-child) scanB ----
        {
            const size_t vi = (size_t)m * N3 + h0;
            float2 z = __half22float2(*(const __half2*)(V1 + vi));
            float2 f = __half22float2(*(const __half2*)(V1 + vi + HID));
            float2 o = __half22float2(*(const __half2*)(V1 + vi + 2 * HID));
            if (CI) {
                const float2 t = *(const float2*)(T1 + (size_t)m * 2);
                const float2 hf = __half22float2(*(const __half2*)(G1F + (size_t)m * HID + h0));
                const float2 ho = __half22float2(*(const __half2*)(G1O + (size_t)m * HID + h0));
                f.x = hf.x * t.x + (1.0f - t.x) * f.x;
                f.y = hf.y * t.x + (1.0f - t.x) * f.y;
                o.x = ho.x * t.y + (1.0f - t.y) * o.x;
                o.y = ho.y * t.y + (1.0f - t.y) * o.y;
            }
            z.x = fmaxf(z.x, 0.0f); z.y = fmaxf(z.y, 0.0f);
            f.x = sigmoidf(f.x);    f.y = sigmoidf(f.y);
            p10 = fmaf(f.x, z.x, (1.0f - f.x) * p10);
            p11 = fmaf(f.y, z.y, (1.0f - f.y) * p11);
            const float h1x = p10 * sigmoidf(o.x) + xr.x;
            const float h1y = p11 * sigmoidf(o.y) + xr.y;
            *(__half2*)&Ho1[(size_t)m * HID + h0] = __floats2half2_rn(h1x, h1y);

            // ---- parent scanA (uses h1 in-register) ----
            const float tp = __ldg(Tp + (size_t)m * 2);
            float2 zp = __half22float2(*(const __half2*)(Vp + vi));
            float2 fp = __half22float2(*(const __half2*)(Vp + vi + HID));
            fp.x = h1x * tp + (1.0f - tp) * fp.x;
            fp.y = h1y * tp + (1.0f - tp) * fp.y;
            zp.x = fmaxf(zp.x, 0.0f); zp.y = fmaxf(zp.y, 0.0f);
            fp.x = sigmoidf(fp.x);    fp.y = sigmoidf(fp.y);
            const float a0 = 1.0f - fp.x, a1 = 1.0f - fp.y;
            PA0 *= a0; PB0 = fmaf(a0, PB0, fp.x * zp.x);
            PA1 *= a1; PB1 = fmaf(a1, PB1, fp.y * zp.y);
        }

        // ---- child 2 (O-child) scanB ----
        {
            const size_t vi = (size_t)m * N3 + h0;
            float2 z = __half22float2(*(const __half2*)(V2 + vi));
            float2 f = __half22float2(*(const __half2*)(V2 + vi + HID));
            float2 o = __half22float2(*(const __half2*)(V2 + vi + 2 * HID));
            if (CI) {
                const float2 t = *(const float2*)(T2 + (size_t)m * 2);
                const float2 hf = __half22float2(*(const __half2*)(G2F + (size_t)m * HID + h0));
                const float2 ho = __half22float2(*(const __half2*)(G2O + (size_t)m * HID + h0));
                f.x = hf.x * t.x + (1.0f - t.x) * f.x;
                f.y = hf.y * t.x + (1.0f - t.x) * f.y;
                o.x = ho.x * t.y + (1.0f - t.y) * o.x;
                o.y = ho.y * t.y + (1.0f - t.y) * o.y;
            }
            z.x = fmaxf(z.x, 0.0f); z.y = fmaxf(z.y, 0.0f);
            f.x = sigmoidf(f.x);    f.y = sigmoidf(f.y);
            p20 = fmaf(f.x, z.x, (1.0f - f.x) * p20);
            p21 = fmaf(f.y, z.y, (1.0f - f.y) * p21);
            const float h2x = p20 * sigmoidf(o.x) + xr.x;
            const float h2y = p21 * sigmoidf(o.y) + xr.y;
            *(__half2*)&Ho2[(size_t)m * HID + h0] = __floats2half2_rn(h2x, h2y);
        }
    }
    const size_t idx = ((size_t)p * NCHUNK + chunk) * LANES + L;
    *(float2*)&g_A[idx]  = make_float2(PA0, PA1);
    *(float2*)&g_Bc[idx] = make_float2(PB0, PB1);
}

// ---------------------------------------------------------------------------
// Root scanB (node 0): merges H[1], H[2], writes out (+X), per-chunk cmax.
// ---------------------------------------------------------------------------
__global__ __launch_bounds__(128) void kroot_kernel(const float* __restrict__ X,
                                                    float* __restrict__ out) {
    const int chunk = blockIdx.y;
    const int l2 = blockIdx.x * 128 + threadIdx.x;
    const int b = l2 >> 8;
    const int h0 = (l2 & 255) * 2;
    const int L = b * 512 + h0;
    const __half* Vn = g_V;                 // node 0
    const float* Tn = g_T;
    const __half* HF = g_Hh;                                  // node 1 -> slot 0
    const __half* HO = g_Hh + (size_t)1 * MROWS * HID;        // node 2 -> slot 1

    float c0 = 0.0f, c1 = 0.0f;
    {
        const float* Ap = g_A  + L;
        const float* Bp = g_Bc + L;
        for (int j = 0; j < chunk; j++) {
            const float2 a  = *(const float2*)(Ap + (size_t)j * LANES);
            const float2 bb = *(const float2*)(Bp + (size_t)j * LANES);
            c0 = fmaf(a.x, c0, bb.x);
            c1 = fmaf(a.y, c1, bb.y);
        }
    }

    float cm0 = -3.4e38f, cm1 = -3.4e38f;
    const int s0 = chunk * CHLEN;
    #pragma unroll 2
    for (int si = 0; si < CHLEN; si++) {
        const int m = (s0 + si) * BATCH + b;
        const size_t vi = (size_t)m * N3 + h0;
        float2 z = __half22float2(*(const __half2*)(Vn + vi));
        float2 f = __half22float2(*(const __half2*)(Vn + vi + HID));
        float2 o = __half22float2(*(const __half2*)(Vn + vi + 2 * HID));
        const float2 t = *(const float2*)(Tn + (size_t)m * 2);
        const float2 hf = __half22float2(*(const __half2*)(HF + (size_t)m * HID + h0));
        const float2 ho = __half22float2(*(const __half2*)(HO + (size_t)m * HID + h0));
        f.x = hf.x * t.x + (1.0f - t.x) * f.x;
        f.y = hf.y * t.x + (1.0f - t.x) * f.y;
        o.x = ho.x * t.y + (1.0f - t.y) * o.x;
        o.y = ho.y * t.y + (1.0f - t.y) * o.y;
        z.x = fmaxf(z.x, 0.0f); z.y = fmaxf(z.y, 0.0f);
        f.x = sigmoidf(f.x);    f.y = sigmoidf(f.y);
        c0 = fmaf(f.x, z.x, (1.0f - f.x) * c0);
        c1 = fmaf(f.y, z.y, (1.0f - f.y) * c1);
        const float v0 = c0 * sigmoidf(o.x);
        const float v1 = c1 * sigmoidf(o.y);
        cm0 = fmaxf(cm0, v0);
        cm1 = fmaxf(cm1, v1);
        const float2 xr = *(const float2*)(X + (size_t)m * DIM + h0);
        *(float2*)&out[(size_t)m * HID + h0] = make_float2(v0 + xr.x, v1 + xr.y);
    }
    *(float2*)&g_CM[(size_t)chunk * LANES + L] = make_float2(cm0, cm1);
}

__global__ __launch_bounds__(128) void cmax_kernel(float* __restrict__ cmax_out) {
    const int lane = blockIdx.x * 128 + threadIdx.x;
    float cm = -3.4e38f;
    #pragma unroll
    for (int j = 0; j < NCHUNK; j++)
        cm = fmaxf(cm, g_CM[(size_t)j * LANES + lane]);
    cmax_out[lane] = cm;
}

// ---------------------------------------------------------------------------
extern "C" void kernel_launch(void* const* d_in, const int* in_sizes, int n_in,
                              void* d_out, int out_size) {
    const float* X  = (const float*)d_in[0];
    const float* Wp = (const float*)d_in[1];
    const float* WT = (const float*)d_in[2];
    const float* bT = (const float*)d_in[3];
    float* out = (float*)d_out;
    (void)in_sizes; (void)n_in;

    // 1-3: prep (ncu profiles launch #4 => the GEMM)
    xround_kernel<<<(MROWS * DIM / 4) / 256, 256>>>(X);
    wround_kernel<<<((size_t)NODES * DIM * N3 / 4) / 256, 256>>>(Wp);
    tproj_kernel<<<MROWS / 128, 128>>>(X, WT, bT);
    // 4: all projections
    gemm_tc_kernel<<<dim3(N3 / BN, MROWS / BM, NODES), 128>>>();
    // 5: leaf chunk summaries
    scanA_leaf_kernel<<<dim3(LANES2 / 128, NCHUNK, 4), 128>>>();
    // 6: scanB(3,4)->scanA(1), scanB(5,6)->scanA(2)
    klevel_kernel<false><<<dim3(LANES2 / 128, NCHUNK, 2), 128>>>(1, X);
    // 7: scanB(1,2)->scanA(0)
    klevel_kernel<true><<<dim3(LANES2 / 128, NCHUNK, 1), 128>>>(0, X);
    // 8: root scanB + per-chunk cmax
    kroot_kernel<<<dim3(LANES2 / 128, NCHUNK), 128>>>(X, out);
    // 9: cmax second output
    if (out_size >= MROWS * HID + LANES)
        cmax_kernel<<<LANES / 128, 128>>>(out + (size_t)MROWS * HID);
}